// round 1
// baseline (speedup 1.0000x reference)
#include <cuda_runtime.h>

#define H 128
#define MAX_ROWS 100000
#define TILE_ROWS 64

// Scratch tables: A = user @ W1_top + b1,  B = movie @ W1_bot
__device__ float g_A[(size_t)MAX_ROWS * H];
__device__ float g_B[(size_t)MAX_ROWS * H];

// ---------------------------------------------------------------------------
// Precompute: out[n_rows, 128] = X[n_rows, 128] @ W[128, 128] (+ bias)
// Block: 64 rows x 128 cols, 256 threads, each thread an 8x4 register tile.
// W (64KB) + X tile (32KB) in dynamic smem.
// ---------------------------------------------------------------------------
__global__ __launch_bounds__(256, 2)
void precompute_kernel(const float* __restrict__ X,
                       const float* __restrict__ W,
                       const float* __restrict__ bias,
                       float* __restrict__ out,
                       int n_rows)
{
    extern __shared__ float smem[];
    float* Ws = smem;              // [128][128]
    float* Xs = smem + H * H;      // [64][128]

    const int tid = threadIdx.x;

    // Load W fully: 16384 floats = 4096 float4, 16 per thread
    {
        const float4* Wv = (const float4*)W;
        float4* Wsv = (float4*)Ws;
        #pragma unroll
        for (int i = 0; i < 16; i++)
            Wsv[tid + i * 256] = Wv[tid + i * 256];
    }

    const int row0 = blockIdx.x * TILE_ROWS;

    // Load X tile: 64 rows x 32 float4 = 2048 float4, 8 per thread
    {
        const float4* Xv = (const float4*)X;
        float4* Xsv = (float4*)Xs;
        #pragma unroll
        for (int i = 0; i < 8; i++) {
            int idx = tid + i * 256;
            int r = idx >> 5;          // 32 float4 per row
            int c = idx & 31;
            float4 v = make_float4(0.f, 0.f, 0.f, 0.f);
            if (row0 + r < n_rows)
                v = Xv[(size_t)(row0 + r) * 32 + c];
            Xsv[idx] = v;
        }
    }
    __syncthreads();

    const int jlane = tid & 31;    // column group: cols jlane*4 .. jlane*4+3
    const int rgrp  = tid >> 5;    // row group: rows rgrp*8 .. rgrp*8+7

    float acc[8][4];
    #pragma unroll
    for (int r = 0; r < 8; r++) {
        acc[r][0] = 0.f; acc[r][1] = 0.f; acc[r][2] = 0.f; acc[r][3] = 0.f;
    }

    #pragma unroll 4
    for (int k = 0; k < H; k += 4) {
        float4 w0 = *(const float4*)&Ws[(k + 0) * H + jlane * 4];
        float4 w1 = *(const float4*)&Ws[(k + 1) * H + jlane * 4];
        float4 w2 = *(const float4*)&Ws[(k + 2) * H + jlane * 4];
        float4 w3 = *(const float4*)&Ws[(k + 3) * H + jlane * 4];
        #pragma unroll
        for (int r = 0; r < 8; r++) {
            float4 x = *(const float4*)&Xs[(rgrp * 8 + r) * H + k];
            acc[r][0] = fmaf(x.x, w0.x, acc[r][0]);
            acc[r][1] = fmaf(x.x, w0.y, acc[r][1]);
            acc[r][2] = fmaf(x.x, w0.z, acc[r][2]);
            acc[r][3] = fmaf(x.x, w0.w, acc[r][3]);
            acc[r][0] = fmaf(x.y, w1.x, acc[r][0]);
            acc[r][1] = fmaf(x.y, w1.y, acc[r][1]);
            acc[r][2] = fmaf(x.y, w1.z, acc[r][2]);
            acc[r][3] = fmaf(x.y, w1.w, acc[r][3]);
            acc[r][0] = fmaf(x.z, w2.x, acc[r][0]);
            acc[r][1] = fmaf(x.z, w2.y, acc[r][1]);
            acc[r][2] = fmaf(x.z, w2.z, acc[r][2]);
            acc[r][3] = fmaf(x.z, w2.w, acc[r][3]);
            acc[r][0] = fmaf(x.w, w3.x, acc[r][0]);
            acc[r][1] = fmaf(x.w, w3.y, acc[r][1]);
            acc[r][2] = fmaf(x.w, w3.z, acc[r][2]);
            acc[r][3] = fmaf(x.w, w3.w, acc[r][3]);
        }
    }

    float4 bv = make_float4(0.f, 0.f, 0.f, 0.f);
    if (bias) bv = *(const float4*)&bias[jlane * 4];

    #pragma unroll
    for (int r = 0; r < 8; r++) {
        int row = row0 + rgrp * 8 + r;
        if (row < n_rows) {
            float4 o;
            o.x = acc[r][0] + bv.x;
            o.y = acc[r][1] + bv.y;
            o.z = acc[r][2] + bv.z;
            o.w = acc[r][3] + bv.w;
            *(float4*)&out[(size_t)row * H + jlane * 4] = o;
        }
    }
}

// ---------------------------------------------------------------------------
// Edge phase: out[e] = relu(A[src[e]] + B[dst[e]]) . W2 + b2
// One warp per edge, 2-edge unroll for memory-level parallelism.
// ---------------------------------------------------------------------------
__global__ __launch_bounds__(256)
void edge_kernel(const int* __restrict__ ei,
                 const float* __restrict__ W2,
                 const float* __restrict__ b2,
                 float* __restrict__ out,
                 int E)
{
    const int lane = threadIdx.x & 31;
    const int gw   = (blockIdx.x * blockDim.x + threadIdx.x) >> 5;
    const int nw   = (gridDim.x * blockDim.x) >> 5;

    const float4 w2 = *(const float4*)&W2[lane * 4];
    const float  b2v = b2[0];

    for (int e0 = gw * 2; e0 < E; e0 += nw * 2) {
        const int e1   = e0 + 1;
        const bool has1 = (e1 < E);
        const int ee1  = has1 ? e1 : e0;

        int s0 = ei[e0], d0 = ei[E + e0];
        int s1 = ei[ee1], d1 = ei[E + ee1];

        float4 a0  = *(const float4*)&g_A[(size_t)s0 * H + lane * 4];
        float4 bb0 = *(const float4*)&g_B[(size_t)d0 * H + lane * 4];
        float4 a1  = *(const float4*)&g_A[(size_t)s1 * H + lane * 4];
        float4 bb1 = *(const float4*)&g_B[(size_t)d1 * H + lane * 4];

        float v0 = fmaxf(a0.x + bb0.x, 0.f) * w2.x
                 + fmaxf(a0.y + bb0.y, 0.f) * w2.y
                 + fmaxf(a0.z + bb0.z, 0.f) * w2.z
                 + fmaxf(a0.w + bb0.w, 0.f) * w2.w;
        float v1 = fmaxf(a1.x + bb1.x, 0.f) * w2.x
                 + fmaxf(a1.y + bb1.y, 0.f) * w2.y
                 + fmaxf(a1.z + bb1.z, 0.f) * w2.z
                 + fmaxf(a1.w + bb1.w, 0.f) * w2.w;

        #pragma unroll
        for (int off = 16; off > 0; off >>= 1) {
            v0 += __shfl_xor_sync(0xFFFFFFFFu, v0, off);
            v1 += __shfl_xor_sync(0xFFFFFFFFu, v1, off);
        }

        if (lane == 0) {
            out[e0] = v0 + b2v;
            if (has1) out[e1] = v1 + b2v;
        }
    }
}

// ---------------------------------------------------------------------------
extern "C" void kernel_launch(void* const* d_in, const int* in_sizes, int n_in,
                              void* d_out, int out_size)
{
    const float* user  = (const float*)d_in[0];
    const float* movie = (const float*)d_in[1];
    const int*   ei    = (const int*)d_in[2];
    const float* W1    = (const float*)d_in[3];
    const float* b1    = (const float*)d_in[4];
    const float* W2    = (const float*)d_in[5];
    const float* b2    = (const float*)d_in[6];
    float* out = (float*)d_out;

    int n_users  = in_sizes[0] / H;
    int n_movies = in_sizes[1] / H;
    int E        = in_sizes[2] / 2;
    if (n_users  > MAX_ROWS) n_users  = MAX_ROWS;
    if (n_movies > MAX_ROWS) n_movies = MAX_ROWS;

    float* dA = nullptr;
    float* dB = nullptr;
    cudaGetSymbolAddress((void**)&dA, g_A);
    cudaGetSymbolAddress((void**)&dB, g_B);

    const int smem_bytes = (H * H + TILE_ROWS * H) * (int)sizeof(float); // 96 KB
    static bool attr_set = false;
    if (!attr_set) {
        cudaFuncSetAttribute(precompute_kernel,
                             cudaFuncAttributeMaxDynamicSharedMemorySize,
                             smem_bytes);
        attr_set = true;
    }

    // A = user @ W1[:128] + b1
    {
        int blocks = (n_users + TILE_ROWS - 1) / TILE_ROWS;
        precompute_kernel<<<blocks, 256, smem_bytes>>>(user, W1, b1, dA, n_users);
    }
    // B = movie @ W1[128:]   (bias folded into A)
    {
        int blocks = (n_movies + TILE_ROWS - 1) / TILE_ROWS;
        precompute_kernel<<<blocks, 256, smem_bytes>>>(movie, W1 + H * H, nullptr, dB, n_movies);
    }
    // Edge scoring
    {
        int blocks = 148 * 8;  // 64 warps/SM at 256 thr/block
        edge_kernel<<<blocks, 256>>>(ei, W2, b2, out, E);
    }
}